// round 8
// baseline (speedup 1.0000x reference)
#include <cuda_runtime.h>
#include <cstdint>

#define NQ       50000
#define MNB      32
#define NKP      15
#define DIN      64
#define DOUT     64
#define OD       45
#define ODP      48
#define KD       960
#define QPB      8
#define NTHREADS 256
#define KSL      60          // k per GEMM slice; 16 slices cover KD

// ---------------- shared memory layout (floats) ----------------
#define SM_WF  0                        // QPB*KD = 7680 (non-dup features)
#define SM_OF  (SM_WF + QPB*KD)         // QPB*ODP = 384
#define SM_KP  (SM_OF + QPB*ODP)        // 48
#define SM_DK  (SM_KP + ODP)            // QPB*ODP = 384
#define SM_OV  (SM_DK + QPB*ODP)        // overlay: AW 4096 / P2 6144 / P4 8192
#define SM_AW  SM_OV
#define SM_P2  SM_OV
#define SM_P4  SM_OV
#define SM_TOT (SM_OV + 8192)
#define SMEM_BYTES (SM_TOT*4)           // 66,752 B -> 3 blocks/SM

// zero-padded offset weights [960][48]
__device__ float g_owpad[KD*ODP];

__global__ void prep_owpad(const float* __restrict__ ow)
{
    int i = blockIdx.x*blockDim.x + threadIdx.x;
    if (i < KD*ODP) {
        int kk = i / ODP, e = i - kk*ODP;
        g_owpad[i] = (e < OD) ? ow[kk*OD + e] : 0.0f;
    }
}

__device__ __forceinline__ uint64_t ffma2(uint64_t a, uint64_t b, uint64_t c)
{
    uint64_t d;
    asm("fma.rn.f32x2 %0, %1, %2, %3;" : "=l"(d) : "l"(a), "l"(b), "l"(c));
    return d;
}
__device__ __forceinline__ uint64_t dup2(float v)
{
    uint64_t d;
    asm("mov.b64 %0, {%1, %1};" : "=l"(d) : "f"(v));
    return d;
}
__device__ __forceinline__ uint64_t pack2(float a, float b)
{
    uint64_t d;
    asm("mov.b64 %0, {%1, %2};" : "=l"(d) : "f"(a), "f"(b));
    return d;
}
__device__ __forceinline__ float lo32(uint64_t v) { return __uint_as_float((uint32_t)v); }
__device__ __forceinline__ float hi32(uint64_t v) { return __uint_as_float((uint32_t)(v >> 32)); }

// Aggregation for query q == warp. Lane owns channel pair (2l, 2l+1).
// K-PAIR packing: aw stored non-dup (16-padded); acc[kpair] per channel.
// Per neighbor: 4 broadcast LDS.128 (aw), 1 LDG.64 (feature), 2 dup movs, 16 FFMA2.
__device__ __forceinline__ void kp_aggregate(
    float* sm, int warp, int lane,
    float nbx, float nby, float nbz, int ni,
    const float* kpp,
    const float* __restrict__ x)
{
    // influence weights for this lane's own neighbor (m = lane), non-dup, pad to 16
    float* awr = sm + SM_AW + warp*512 + lane*16;
    float wv[16];
#pragma unroll
    for (int k = 0; k < NKP; k++) {
        float dx = nbx - kpp[3*k+0];
        float dy = nby - kpp[3*k+1];
        float dz = nbz - kpp[3*k+2];
        float d  = sqrtf(fmaf(dx, dx, fmaf(dy, dy, dz*dz)));
        wv[k] = fmaxf(1.0f - d, 0.0f);
    }
    wv[15] = 0.0f;
    *(float4*)(awr + 0)  = make_float4(wv[0],  wv[1],  wv[2],  wv[3]);
    *(float4*)(awr + 4)  = make_float4(wv[4],  wv[5],  wv[6],  wv[7]);
    *(float4*)(awr + 8)  = make_float4(wv[8],  wv[9],  wv[10], wv[11]);
    *(float4*)(awr + 12) = make_float4(wv[12], wv[13], wv[14], wv[15]);
    __syncwarp();

    uint64_t ac0[8], ac1[8];   // kpair accs for channels c0, c1
#pragma unroll
    for (int kp = 0; kp < 8; kp++) { ac0[kp] = 0ull; ac1[kp] = 0ull; }

    const float* awb = sm + SM_AW + warp*512;

#pragma unroll 4
    for (int m = 0; m < MNB; m++) {
        int n = __shfl_sync(0xffffffffu, ni, m);
        float2 f = *(const float2*)(x + n*DIN + 2*lane);   // LDG.64, coalesced
        uint64_t d0 = dup2(f.x), d1 = dup2(f.y);
        const ulonglong2* ar = (const ulonglong2*)(awb + m*16);  // 4 broadcast LDS.128
        ulonglong2 a0 = ar[0], a1 = ar[1];
        ac0[0] = ffma2(a0.x, d0, ac0[0]);  ac1[0] = ffma2(a0.x, d1, ac1[0]);
        ac0[1] = ffma2(a0.y, d0, ac0[1]);  ac1[1] = ffma2(a0.y, d1, ac1[1]);
        ac0[2] = ffma2(a1.x, d0, ac0[2]);  ac1[2] = ffma2(a1.x, d1, ac1[2]);
        ac0[3] = ffma2(a1.y, d0, ac0[3]);  ac1[3] = ffma2(a1.y, d1, ac1[3]);
        ulonglong2 a2 = ar[2], a3 = ar[3];
        ac0[4] = ffma2(a2.x, d0, ac0[4]);  ac1[4] = ffma2(a2.x, d1, ac1[4]);
        ac0[5] = ffma2(a2.y, d0, ac0[5]);  ac1[5] = ffma2(a2.y, d1, ac1[5]);
        ac0[6] = ffma2(a3.x, d0, ac0[6]);  ac1[6] = ffma2(a3.x, d1, ac1[6]);
        ac0[7] = ffma2(a3.y, d0, ac0[7]);  ac1[7] = ffma2(a3.y, d1, ac1[7]);
    }

    // repack in-register and store WF[q][k*64 + 2*lane] (STS.64 conflict-free)
    float* wr = sm + SM_WF + warp*KD;
#pragma unroll
    for (int kp = 0; kp < 8; kp++) {
        *(uint64_t*)(wr + (2*kp)*DIN + 2*lane) = pack2(lo32(ac0[kp]), lo32(ac1[kp]));
        if (2*kp + 1 < NKP)
            *(uint64_t*)(wr + (2*kp+1)*DIN + 2*lane) = pack2(hi32(ac0[kp]), hi32(ac1[kp]));
    }
}

__global__ __launch_bounds__(NTHREADS, 3)
void kpconv_deform_fused(
    const float* __restrict__ qp,    // [N,3]
    const float* __restrict__ sp,    // [N,3]
    const int*   __restrict__ neigh, // [N,32]
    const float* __restrict__ x,     // [N,64]
    const float* __restrict__ kpts,  // [15,3]
    const float* __restrict__ obias, // [45]
    const float* __restrict__ w,     // [960,64]
    float*       __restrict__ out)   // [N,64]
{
    extern __shared__ float sm[];
    const int tid  = threadIdx.x;
    const int lane = tid & 31;
    const int warp = tid >> 5;
    const int h    = (lane >> 4) & 1;
    const int j    = lane & 15;
    const int q0   = blockIdx.x * QPB;
    const int q    = q0 + warp;

    if (tid < OD) sm[SM_KP + tid] = kpts[tid];

    // neighbor geometry, registers only (lane = its own neighbor m)
    float qx = qp[q*3+0], qy = qp[q*3+1], qz = qp[q*3+2];
    int   ni = neigh[q*MNB + lane];
    float nbx = sp[ni*3+0] - qx;
    float nby = sp[ni*3+1] - qy;
    float nbz = sp[ni*3+2] - qz;
    __syncthreads();

    // -------- Phase 1: rigid aggregation -> WF1 --------
    kp_aggregate(sm, warp, lane, nbx, nby, nbz, ni, sm + SM_KP, x);
    __syncthreads();

    // -------- Phase 2: offset GEMM  OF[8][48] = WF1[8][960] @ OWpad[960][48] --------
    {
        const int slice = warp*2 + h;        // 0..15
        const int kk0   = slice * KSL;
        uint64_t aclo[QPB], achi[QPB];
#pragma unroll
        for (int qi = 0; qi < QPB; qi++) { aclo[qi] = 0ull; achi[qi] = 0ull; }
        if (j < 12) {
            for (int kk = kk0; kk < kk0 + KSL; kk += 4) {
                ulonglong2 wA = *(const ulonglong2*)(g_owpad + (kk+0)*ODP + 4*j);
                ulonglong2 wB = *(const ulonglong2*)(g_owpad + (kk+1)*ODP + 4*j);
                ulonglong2 wC = *(const ulonglong2*)(g_owpad + (kk+2)*ODP + 4*j);
                ulonglong2 wD = *(const ulonglong2*)(g_owpad + (kk+3)*ODP + 4*j);
#pragma unroll
                for (int qi = 0; qi < QPB; qi++) {
                    float4 f = *(const float4*)(sm + SM_WF + qi*KD + kk);  // LDS.128 broadcast
                    uint64_t d0 = dup2(f.x), d1 = dup2(f.y);
                    aclo[qi] = ffma2(d0, wA.x, aclo[qi]);
                    achi[qi] = ffma2(d0, wA.y, achi[qi]);
                    aclo[qi] = ffma2(d1, wB.x, aclo[qi]);
                    achi[qi] = ffma2(d1, wB.y, achi[qi]);
                    uint64_t d2 = dup2(f.z), d3 = dup2(f.w);
                    aclo[qi] = ffma2(d2, wC.x, aclo[qi]);
                    achi[qi] = ffma2(d2, wC.y, achi[qi]);
                    aclo[qi] = ffma2(d3, wD.x, aclo[qi]);
                    achi[qi] = ffma2(d3, wD.y, achi[qi]);
                }
            }
        }
        __syncthreads();   // phase-1 AW reads done before P2 overlay stores
        if (j < 12) {
#pragma unroll
            for (int qi = 0; qi < QPB; qi++)
                *(ulonglong2*)(sm + SM_P2 + slice*384 + qi*48 + 4*j) =
                    make_ulonglong2(aclo[qi], achi[qi]);
        }
    }
    __syncthreads();

    // reduce 16 k-slices -> OF (+bias)
    if (tid < 192) {
        int qi = tid / 24, ep = tid % 24, e = 2*ep;
        float sx = 0.f, sy = 0.f;
#pragma unroll
        for (int s = 0; s < 16; s++) {
            float2 p = *(const float2*)(sm + SM_P2 + s*384 + qi*48 + e);
            sx += p.x; sy += p.y;
        }
        sx += (e   < OD) ? obias[e]   : 0.f;
        sy += (e+1 < OD) ? obias[e+1] : 0.f;
        *(float2*)(sm + SM_OF + qi*ODP + e) = make_float2(sx, sy);
    }
    __syncthreads();

    // -------- Phase 3: deformed kernel points + aggregation -> WF2 --------
    for (int t2 = lane; t2 < OD; t2 += 32)
        sm[SM_DK + warp*ODP + t2] = sm[SM_KP + t2] + sm[SM_OF + warp*ODP + t2];
    __syncwarp();
    kp_aggregate(sm, warp, lane, nbx, nby, nbz, ni, sm + SM_DK + warp*ODP, x);
    __syncthreads();

    // -------- Phase 4: output GEMM  out[8][64] = WF2[8][960] @ W[960][64] --------
    {
        const int slice = warp*2 + h;
        const int kk0   = slice * KSL;
        uint64_t aclo[QPB], achi[QPB];
#pragma unroll
        for (int qi = 0; qi < QPB; qi++) { aclo[qi] = 0ull; achi[qi] = 0ull; }
        for (int kk = kk0; kk < kk0 + KSL; kk += 4) {
            ulonglong2 wA = *(const ulonglong2*)(w + (kk+0)*DOUT + 4*j);
            ulonglong2 wB = *(const ulonglong2*)(w + (kk+1)*DOUT + 4*j);
            ulonglong2 wC = *(const ulonglong2*)(w + (kk+2)*DOUT + 4*j);
            ulonglong2 wD = *(const ulonglong2*)(w + (kk+3)*DOUT + 4*j);
#pragma unroll
            for (int qi = 0; qi < QPB; qi++) {
                float4 f = *(const float4*)(sm + SM_WF + qi*KD + kk);
                uint64_t d0 = dup2(f.x), d1 = dup2(f.y);
                aclo[qi] = ffma2(d0, wA.x, aclo[qi]);
                achi[qi] = ffma2(d0, wA.y, achi[qi]);
                aclo[qi] = ffma2(d1, wB.x, aclo[qi]);
                achi[qi] = ffma2(d1, wB.y, achi[qi]);
                uint64_t d2 = dup2(f.z), d3 = dup2(f.w);
                aclo[qi] = ffma2(d2, wC.x, aclo[qi]);
                achi[qi] = ffma2(d2, wC.y, achi[qi]);
                aclo[qi] = ffma2(d3, wD.x, aclo[qi]);
                achi[qi] = ffma2(d3, wD.y, achi[qi]);
            }
        }
#pragma unroll
        for (int qi = 0; qi < QPB; qi++)
            *(ulonglong2*)(sm + SM_P4 + slice*512 + qi*64 + 4*j) =
                make_ulonglong2(aclo[qi], achi[qi]);
    }
    __syncthreads();

    // reduce 16 k-slices -> global out
    {
        int qi = tid >> 5, e = (tid & 31) * 2;
        float sx = 0.f, sy = 0.f;
#pragma unroll
        for (int s = 0; s < 16; s++) {
            float2 p = *(const float2*)(sm + SM_P4 + s*512 + qi*64 + e);
            sx += p.x; sy += p.y;
        }
        *(float2*)(out + (q0 + qi)*DOUT + e) = make_float2(sx, sy);
    }
}

extern "C" void kernel_launch(void* const* d_in, const int* in_sizes, int n_in,
                              void* d_out, int out_size)
{
    const float* qp    = (const float*)d_in[0];
    const float* sp    = (const float*)d_in[1];
    const int*   neigh = (const int*)  d_in[2];
    const float* x     = (const float*)d_in[3];
    const float* kpts  = (const float*)d_in[4];
    const float* ow    = (const float*)d_in[5];
    const float* obias = (const float*)d_in[6];
    const float* w     = (const float*)d_in[7];
    float* out = (float*)d_out;

    prep_owpad<<<(KD*ODP + 255)/256, 256>>>(ow);

    cudaFuncSetAttribute(kpconv_deform_fused,
                         cudaFuncAttributeMaxDynamicSharedMemorySize, SMEM_BYTES);

    kpconv_deform_fused<<<NQ/QPB, NTHREADS, SMEM_BYTES>>>(
        qp, sp, neigh, x, kpts, obias, w, out);
}

// round 9
// speedup vs baseline: 1.6267x; 1.6267x over previous
#include <cuda_runtime.h>
#include <cstdint>

#define NQ       50000
#define MNB      32
#define NKP      15
#define DIN      64
#define DOUT     64
#define OD       45
#define ODP      48
#define KD       960
#define QPB      8
#define NTHREADS 256
#define KSL      60          // k per GEMM slice; 16 slices cover KD

// ---------------- shared memory layout (floats) ----------------
#define SM_WF  0                        // QPB*KD = 7680 (non-dup features)
#define SM_OF  (SM_WF + QPB*KD)         // QPB*ODP = 384
#define SM_KP  (SM_OF + QPB*ODP)        // 48
#define SM_DK  (SM_KP + ODP)            // QPB*ODP = 384
#define SM_OV  (SM_DK + QPB*ODP)        // overlay: AW 6144 / P2 6144 / P4 8192
#define SM_AW  SM_OV
#define SM_P2  SM_OV
#define SM_P4  SM_OV
#define SM_TOT (SM_OV + 8192)
#define SMEM_BYTES (SM_TOT*4)           // 66,752 B -> 3 blocks/SM

// zero-padded offset weights [960][48]
__device__ float g_owpad[KD*ODP];

__global__ void prep_owpad(const float* __restrict__ ow)
{
    int i = blockIdx.x*blockDim.x + threadIdx.x;
    if (i < KD*ODP) {
        int kk = i / ODP, e = i - kk*ODP;
        g_owpad[i] = (e < OD) ? ow[kk*OD + e] : 0.0f;
    }
}

__device__ __forceinline__ uint64_t ffma2(uint64_t a, uint64_t b, uint64_t c)
{
    uint64_t d;
    asm("fma.rn.f32x2 %0, %1, %2, %3;" : "=l"(d) : "l"(a), "l"(b), "l"(c));
    return d;
}
__device__ __forceinline__ uint64_t dup2(float v)
{
    uint64_t d;
    asm("mov.b64 %0, {%1, %1};" : "=l"(d) : "f"(v));
    return d;
}
__device__ __forceinline__ uint64_t pack2(float a, float b)
{
    uint64_t d;
    asm("mov.b64 %0, {%1, %2};" : "=l"(d) : "f"(a), "f"(b));
    return d;
}
__device__ __forceinline__ float lo32(uint64_t v) { return __uint_as_float((uint32_t)v); }
__device__ __forceinline__ float hi32(uint64_t v) { return __uint_as_float((uint32_t)(v >> 32)); }

// Aggregation for query q == warp. Lane owns channel pair (2l, 2l+1).
// K-pair FFMA2 packing: aw non-dup (16 vals, row stride 24 floats = 96B so every
// row is 16B-aligned). Per neighbor: 4 broadcast LDS.128 + 1 LDG.64 + 2 dup movs
// + 16 FFMA2. WF repacked in-register to the standard [k][ch] layout (STS.64).
__device__ __forceinline__ void kp_aggregate(
    float* sm, int warp, int lane,
    float nbx, float nby, float nbz, int ni,
    const float* kpp,
    const float* __restrict__ x)
{
    float* awr = sm + SM_AW + warp*768 + lane*24;
    {
        float wv[16];
#pragma unroll
        for (int k = 0; k < NKP; k++) {
            float dx = nbx - kpp[3*k+0];
            float dy = nby - kpp[3*k+1];
            float dz = nbz - kpp[3*k+2];
            float d  = sqrtf(fmaf(dx, dx, fmaf(dy, dy, dz*dz)));
            wv[k] = fmaxf(1.0f - d, 0.0f);
        }
        wv[15] = 0.0f;
        *(float4*)(awr + 0)  = make_float4(wv[0],  wv[1],  wv[2],  wv[3]);
        *(float4*)(awr + 4)  = make_float4(wv[4],  wv[5],  wv[6],  wv[7]);
        *(float4*)(awr + 8)  = make_float4(wv[8],  wv[9],  wv[10], wv[11]);
        *(float4*)(awr + 12) = make_float4(wv[12], wv[13], wv[14], wv[15]);
    }
    __syncwarp();

    uint64_t ac0[8], ac1[8];   // k-pair accumulators for channels c0, c1
#pragma unroll
    for (int kp = 0; kp < 8; kp++) { ac0[kp] = 0ull; ac1[kp] = 0ull; }

    const float* awb = sm + SM_AW + warp*768;

#pragma unroll 4
    for (int m = 0; m < MNB; m++) {
        int n = __shfl_sync(0xffffffffu, ni, m);
        float2 f = *(const float2*)(x + n*DIN + 2*lane);   // LDG.64, coalesced
        uint64_t d0 = dup2(f.x), d1 = dup2(f.y);
        const ulonglong2* ar = (const ulonglong2*)(awb + m*24);  // 4 broadcast LDS.128
        {
            ulonglong2 a0 = ar[0], a1 = ar[1];
            ac0[0] = ffma2(a0.x, d0, ac0[0]);  ac1[0] = ffma2(a0.x, d1, ac1[0]);
            ac0[1] = ffma2(a0.y, d0, ac0[1]);  ac1[1] = ffma2(a0.y, d1, ac1[1]);
            ac0[2] = ffma2(a1.x, d0, ac0[2]);  ac1[2] = ffma2(a1.x, d1, ac1[2]);
            ac0[3] = ffma2(a1.y, d0, ac0[3]);  ac1[3] = ffma2(a1.y, d1, ac1[3]);
        }
        {
            ulonglong2 a2 = ar[2], a3 = ar[3];
            ac0[4] = ffma2(a2.x, d0, ac0[4]);  ac1[4] = ffma2(a2.x, d1, ac1[4]);
            ac0[5] = ffma2(a2.y, d0, ac0[5]);  ac1[5] = ffma2(a2.y, d1, ac1[5]);
            ac0[6] = ffma2(a3.x, d0, ac0[6]);  ac1[6] = ffma2(a3.x, d1, ac1[6]);
            ac0[7] = ffma2(a3.y, d0, ac0[7]);  ac1[7] = ffma2(a3.y, d1, ac1[7]);
        }
    }

    // repack to WF[q][k*64 + 2*lane] (STS.64 conflict-free); k=15 is pad, skipped
    float* wr = sm + SM_WF + warp*KD;
#pragma unroll
    for (int kp = 0; kp < 7; kp++) {
        *(uint64_t*)(wr + (2*kp)*DIN   + 2*lane) = pack2(lo32(ac0[kp]), lo32(ac1[kp]));
        *(uint64_t*)(wr + (2*kp+1)*DIN + 2*lane) = pack2(hi32(ac0[kp]), hi32(ac1[kp]));
    }
    *(uint64_t*)(wr + 14*DIN + 2*lane) = pack2(lo32(ac0[7]), lo32(ac1[7]));
}

__global__ __launch_bounds__(NTHREADS, 3)
void kpconv_deform_fused(
    const float* __restrict__ qp,    // [N,3]
    const float* __restrict__ sp,    // [N,3]
    const int*   __restrict__ neigh, // [N,32]
    const float* __restrict__ x,     // [N,64]
    const float* __restrict__ kpts,  // [15,3]
    const float* __restrict__ obias, // [45]
    const float* __restrict__ w,     // [960,64]
    float*       __restrict__ out)   // [N,64]
{
    extern __shared__ float sm[];
    const int tid  = threadIdx.x;
    const int lane = tid & 31;
    const int warp = tid >> 5;
    const int h    = (lane >> 4) & 1;
    const int j    = lane & 15;
    const int q0   = blockIdx.x * QPB;
    const int q    = q0 + warp;

    if (tid < OD) sm[SM_KP + tid] = kpts[tid];

    // neighbor geometry, registers only (lane = its own neighbor m)
    float qx = qp[q*3+0], qy = qp[q*3+1], qz = qp[q*3+2];
    int   ni = neigh[q*MNB + lane];
    float nbx = sp[ni*3+0] - qx;
    float nby = sp[ni*3+1] - qy;
    float nbz = sp[ni*3+2] - qz;
    __syncthreads();

    // -------- Phase 1: rigid aggregation -> WF1 --------
    kp_aggregate(sm, warp, lane, nbx, nby, nbz, ni, sm + SM_KP, x);
    __syncthreads();

    // -------- Phase 2: offset GEMM  OF[8][48] = WF1[8][960] @ OWpad[960][48] --------
    {
        const int slice = warp*2 + h;        // 0..15
        const int kk0   = slice * KSL;
        uint64_t aclo[QPB], achi[QPB];
#pragma unroll
        for (int qi = 0; qi < QPB; qi++) { aclo[qi] = 0ull; achi[qi] = 0ull; }
        if (j < 12) {
            for (int kk = kk0; kk < kk0 + KSL; kk += 2) {
                ulonglong2 wA = *(const ulonglong2*)(g_owpad + kk*ODP     + 4*j);
                ulonglong2 wB = *(const ulonglong2*)(g_owpad + (kk+1)*ODP + 4*j);
#pragma unroll
                for (int qi = 0; qi < QPB; qi++) {
                    float2 f = *(const float2*)(sm + SM_WF + qi*KD + kk);  // broadcast LDS.64
                    uint64_t dx = dup2(f.x), dy = dup2(f.y);
                    aclo[qi] = ffma2(dx, wA.x, aclo[qi]);
                    achi[qi] = ffma2(dx, wA.y, achi[qi]);
                    aclo[qi] = ffma2(dy, wB.x, aclo[qi]);
                    achi[qi] = ffma2(dy, wB.y, achi[qi]);
                }
            }
        }
        __syncthreads();   // phase-1 AW reads done before P2 overlay stores
        if (j < 12) {
#pragma unroll
            for (int qi = 0; qi < QPB; qi++)
                *(ulonglong2*)(sm + SM_P2 + slice*384 + qi*48 + 4*j) =
                    make_ulonglong2(aclo[qi], achi[qi]);
        }
    }
    __syncthreads();

    // reduce 16 k-slices -> OF (+bias)
    if (tid < 192) {
        int qi = tid / 24, ep = tid % 24, e = 2*ep;
        float sx = 0.f, sy = 0.f;
#pragma unroll
        for (int s = 0; s < 16; s++) {
            float2 p = *(const float2*)(sm + SM_P2 + s*384 + qi*48 + e);
            sx += p.x; sy += p.y;
        }
        sx += (e   < OD) ? obias[e]   : 0.f;
        sy += (e+1 < OD) ? obias[e+1] : 0.f;
        *(float2*)(sm + SM_OF + qi*ODP + e) = make_float2(sx, sy);
    }
    __syncthreads();

    // -------- Phase 3: deformed kernel points + aggregation -> WF2 --------
    for (int t2 = lane; t2 < OD; t2 += 32)
        sm[SM_DK + warp*ODP + t2] = sm[SM_KP + t2] + sm[SM_OF + warp*ODP + t2];
    __syncwarp();
    kp_aggregate(sm, warp, lane, nbx, nby, nbz, ni, sm + SM_DK + warp*ODP, x);
    __syncthreads();

    // -------- Phase 4: output GEMM  out[8][64] = WF2[8][960] @ W[960][64] --------
    {
        const int slice = warp*2 + h;
        const int kk0   = slice * KSL;
        uint64_t aclo[QPB], achi[QPB];
#pragma unroll
        for (int qi = 0; qi < QPB; qi++) { aclo[qi] = 0ull; achi[qi] = 0ull; }
        for (int kk = kk0; kk < kk0 + KSL; kk += 2) {
            ulonglong2 wA = *(const ulonglong2*)(w + kk*DOUT     + 4*j);
            ulonglong2 wB = *(const ulonglong2*)(w + (kk+1)*DOUT + 4*j);
#pragma unroll
            for (int qi = 0; qi < QPB; qi++) {
                float2 f = *(const float2*)(sm + SM_WF + qi*KD + kk);
                uint64_t dx = dup2(f.x), dy = dup2(f.y);
                aclo[qi] = ffma2(dx, wA.x, aclo[qi]);
                achi[qi] = ffma2(dx, wA.y, achi[qi]);
                aclo[qi] = ffma2(dy, wB.x, aclo[qi]);
                achi[qi] = ffma2(dy, wB.y, achi[qi]);
            }
        }
#pragma unroll
        for (int qi = 0; qi < QPB; qi++)
            *(ulonglong2*)(sm + SM_P4 + slice*512 + qi*64 + 4*j) =
                make_ulonglong2(aclo[qi], achi[qi]);
    }
    __syncthreads();

    // reduce 16 k-slices -> global out
    {
        int qi = tid >> 5, e = (tid & 31) * 2;
        float sx = 0.f, sy = 0.f;
#pragma unroll
        for (int s = 0; s < 16; s++) {
            float2 p = *(const float2*)(sm + SM_P4 + s*512 + qi*64 + e);
            sx += p.x; sy += p.y;
        }
        *(float2*)(out + (q0 + qi)*DOUT + e) = make_float2(sx, sy);
    }
}

extern "C" void kernel_launch(void* const* d_in, const int* in_sizes, int n_in,
                              void* d_out, int out_size)
{
    const float* qp    = (const float*)d_in[0];
    const float* sp    = (const float*)d_in[1];
    const int*   neigh = (const int*)  d_in[2];
    const float* x     = (const float*)d_in[3];
    const float* kpts  = (const float*)d_in[4];
    const float* ow    = (const float*)d_in[5];
    const float* obias = (const float*)d_in[6];
    const float* w     = (const float*)d_in[7];
    float* out = (float*)d_out;

    prep_owpad<<<(KD*ODP + 255)/256, 256>>>(ow);

    cudaFuncSetAttribute(kpconv_deform_fused,
                         cudaFuncAttributeMaxDynamicSharedMemorySize, SMEM_BYTES);

    kpconv_deform_fused<<<NQ/QPB, NTHREADS, SMEM_BYTES>>>(
        qp, sp, neigh, x, kpts, obias, w, out);
}